// round 11
// baseline (speedup 1.0000x reference)
#include <cuda_runtime.h>
#include <cstdint>

#define FULLMASK 0xFFFFFFFFu

constexpr int GRID1 = 148;           // one 512-thread block per SM
constexpr int T1    = 512;           // 16 warps -> 128 regs/thread available
constexpr int PART_STRIDE = 128 * 128 + 256;  // s[16384] + n[128] + Q[128]
constexpr int WIN   = 1024;          // token-code window in smem

// Partial accumulators: 148 * 16640 floats ~= 9.85 MB (static device array)
__device__ __align__(16) float g_part[(size_t)GRID1 * PART_STRIDE];
__device__ float g_tot;
__device__ float g_cntf;
__device__ unsigned g_done;          // monotonic finish counter (never reset)

// ---------------------------------------------------------------------------
// Kernel 1: one-token-per-warp softmax, register-resident accumulators.
// 16 warps/block; warp w owns segments {sg : sg&15 == w} (8 rows = 8 float4/lane).
// 512 threads => 128 regs/thread: the whole state fits with NO spills.
// ---------------------------------------------------------------------------
__global__ void __launch_bounds__(T1, 1)
k1_accumulate(const float* __restrict__ logits,
              const int*   __restrict__ segs,
              const void*  __restrict__ maskp,
              int N)
{
    __shared__ unsigned char code[WIN];   // seg | 0xFF per token

    const int tid  = threadIdx.x;
    const int lane = tid & 31;
    const int wid  = tid >> 5;   // 0..15

    if (blockIdx.x == 0 && tid == 0) { g_tot = 0.0f; g_cntf = 0.0f; }

    // --- Detect mask dtype (bool/uint8 vs int32) from byte pattern ---------
    int local_nz = 0;
    {
        const unsigned char* mb = (const unsigned char*)maskp;
        int lim = (N < 1024) ? N : 1024;
        for (int p = tid; p < lim; p += T1)
            if ((p & 3) && mb[p]) local_nz = 1;
    }
    const int is_bool = __syncthreads_or(local_nz);

    const int chunk = (N + GRID1 - 1) / GRID1;
    const int cbeg  = blockIdx.x * chunk;
    const int cend  = min(N, cbeg + chunk);

    const unsigned char* m8  = (const unsigned char*)maskp;
    const int*           m32 = (const int*)maskp;
    const float4* lg4 = (const float4*)logits;

    // --- Register accumulators: 8 owned segments per warp -------------------
    const float4 z4 = make_float4(0.f, 0.f, 0.f, 0.f);
    float4 a0 = z4, a1 = z4, a2 = z4, a3 = z4, a4 = z4, a5 = z4, a6 = z4, a7 = z4;
    float n0 = 0.f, n1 = 0.f, n2 = 0.f, n3 = 0.f, n4 = 0.f, n5 = 0.f, n6 = 0.f, n7 = 0.f;
    float q0 = 0.f, q1 = 0.f, q2 = 0.f, q3 = 0.f, q4 = 0.f, q5 = 0.f, q6 = 0.f, q7 = 0.f;

    for (int wb = cbeg; wb < cend; wb += WIN) {
        const int wlen = min(cend - wb, WIN);
        __syncthreads();
        for (int i = tid; i < wlen; i += T1) {
            int sg = segs[wb + i] & 127;
            int v  = is_bool ? (m8[wb + i] != 0) : (m32[wb + i] != 0);
            code[i] = v ? (unsigned char)sg : (unsigned char)0xFF;
        }
        __syncthreads();

        // --- Warp-uniform scan: warp owns tokens with seg&15 == wid ---------
        int gpos = 0;
        unsigned msk = 0;
        unsigned myc = 0xFFu;

        auto pop = [&](int& tok, int& sg) -> bool {
            while (msk == 0u && gpos < wlen) {
                int idx = gpos + lane;
                unsigned c = (idx < wlen) ? (unsigned)code[idx] : 0xFFu;
                bool own = (c != 0xFFu) && ((c & 15u) == (unsigned)wid);
                msk = __ballot_sync(FULLMASK, own);
                myc = c;
                gpos += 32;
            }
            if (msk == 0u) return false;
            int b = __ffs(msk) - 1;
            msk &= (msk - 1u);
            tok = wb + (gpos - 32) + b;
            sg  = __shfl_sync(FULLMASK, (int)myc, b) & 127;
            return true;
        };

        auto process = [&](int sg, float4 x) {
            float4 e;
            e.x = __expf(x.x); e.y = __expf(x.y);
            e.z = __expf(x.z); e.w = __expf(x.w);
            float se = (e.x + e.y) + (e.z + e.w);
            float q  = (e.x*e.x + e.y*e.y) + (e.z*e.z + e.w*e.w);
            #pragma unroll
            for (int o = 16; o; o >>= 1) {
                se += __shfl_xor_sync(FULLMASK, se, o);
                q  += __shfl_xor_sync(FULLMASK, q,  o);
            }
            const float inv = __frcp_rn(se);
            const float qn  = q * inv * inv;
            const int idx = sg >> 4;            // warp-uniform 0..7
            switch (idx) {
            case 0: a0.x += e.x*inv; a0.y += e.y*inv; a0.z += e.z*inv; a0.w += e.w*inv;
                    n0 += 1.0f; q0 += qn; break;
            case 1: a1.x += e.x*inv; a1.y += e.y*inv; a1.z += e.z*inv; a1.w += e.w*inv;
                    n1 += 1.0f; q1 += qn; break;
            case 2: a2.x += e.x*inv; a2.y += e.y*inv; a2.z += e.z*inv; a2.w += e.w*inv;
                    n2 += 1.0f; q2 += qn; break;
            case 3: a3.x += e.x*inv; a3.y += e.y*inv; a3.z += e.z*inv; a3.w += e.w*inv;
                    n3 += 1.0f; q3 += qn; break;
            case 4: a4.x += e.x*inv; a4.y += e.y*inv; a4.z += e.z*inv; a4.w += e.w*inv;
                    n4 += 1.0f; q4 += qn; break;
            case 5: a5.x += e.x*inv; a5.y += e.y*inv; a5.z += e.z*inv; a5.w += e.w*inv;
                    n5 += 1.0f; q5 += qn; break;
            case 6: a6.x += e.x*inv; a6.y += e.y*inv; a6.z += e.z*inv; a6.w += e.w*inv;
                    n6 += 1.0f; q6 += qn; break;
            default:a7.x += e.x*inv; a7.y += e.y*inv; a7.z += e.z*inv; a7.w += e.w*inv;
                    n7 += 1.0f; q7 += qn; break;
            }
        };

        // --- Depth-3 pipeline: two tokens prefetched ahead ------------------
        int tA, sA = 0, tB, sB = 0, tC, sC = 0;
        float4 vA = z4, vB = z4, vC = z4;
        bool hA = pop(tA, sA);
        if (hA) vA = __ldg(lg4 + (size_t)tA * 32 + lane);
        bool hB = pop(tB, sB);
        if (hB) vB = __ldg(lg4 + (size_t)tB * 32 + lane);
        bool hC = pop(tC, sC);
        if (hC) vC = __ldg(lg4 + (size_t)tC * 32 + lane);

        while (hA) {
            int tD, sD = 0;
            float4 vD = z4;
            bool hD = pop(tD, sD);
            if (hD) vD = __ldg(lg4 + (size_t)tD * 32 + lane);

            process(sA, vA);

            sA = sB; vA = vB; hA = hB;
            sB = sC; vB = vC; hB = hC;
            sC = sD; vC = vD; hC = hD;
        }
    }

    // --- Flush register accumulators straight to the global slab ------------
    {
        float* base = g_part + (size_t)blockIdx.x * PART_STRIDE;
        ((float4*)(base + (wid       ) * 128))[lane] = a0;
        ((float4*)(base + (wid +  16 ) * 128))[lane] = a1;
        ((float4*)(base + (wid +  32 ) * 128))[lane] = a2;
        ((float4*)(base + (wid +  48 ) * 128))[lane] = a3;
        ((float4*)(base + (wid +  64 ) * 128))[lane] = a4;
        ((float4*)(base + (wid +  80 ) * 128))[lane] = a5;
        ((float4*)(base + (wid +  96 ) * 128))[lane] = a6;
        ((float4*)(base + (wid + 112 ) * 128))[lane] = a7;
        if (lane == 0) {
            base[16384 + wid      ] = n0;  base[16512 + wid      ] = q0;
            base[16384 + wid +  16] = n1;  base[16512 + wid +  16] = q1;
            base[16384 + wid +  32] = n2;  base[16512 + wid +  32] = q2;
            base[16384 + wid +  48] = n3;  base[16512 + wid +  48] = q3;
            base[16384 + wid +  64] = n4;  base[16512 + wid +  64] = q4;
            base[16384 + wid +  80] = n5;  base[16512 + wid +  80] = q5;
            base[16384 + wid +  96] = n6;  base[16512 + wid +  96] = q6;
            base[16384 + wid + 112] = n7;  base[16512 + wid + 112] = q7;
        }
    }
}

// ---------------------------------------------------------------------------
// Kernel 2: one block per segment (1024 threads), slab reduction with MLP-4
// partial accumulators, closed-form variance, final combine.
// ---------------------------------------------------------------------------
__global__ void __launch_bounds__(1024)
k2_final(float* __restrict__ out)
{
    __shared__ float sred[8][128];
    __shared__ float sc_n, sc_q, sc_s2[4];

    const int c    = blockIdx.x;     // segment id
    const int tid  = threadIdx.x;
    const int lane = tid & 31;
    const int wid  = tid >> 5;
    const int col  = tid & 127;      // column within the segment row
    const int grp  = tid >> 7;       // 0..7 slab groups

    if (tid == 0) { sc_n = 0.0f; sc_q = 0.0f; }

    // 19 strided slab reads per thread, 4 rotating partials for MLP
    float ps[4] = {0.f, 0.f, 0.f, 0.f};
    #pragma unroll
    for (int k = 0; k < 19; k++) {
        int b = grp + k * 8;
        float v = (b < GRID1) ? g_part[(size_t)b * PART_STRIDE + c * 128 + col] : 0.0f;
        ps[k & 3] += v;
    }
    sred[grp][col] = (ps[0] + ps[1]) + (ps[2] + ps[3]);

    float nn = 0.0f, qq = 0.0f;
    if (tid < GRID1) {
        nn = g_part[(size_t)tid * PART_STRIDE + 16384 + c];
        qq = g_part[(size_t)tid * PART_STRIDE + 16512 + c];
    }
    #pragma unroll
    for (int o = 16; o; o >>= 1) {
        nn += __shfl_xor_sync(FULLMASK, nn, o);
        qq += __shfl_xor_sync(FULLMASK, qq, o);
    }
    __syncthreads();
    if (lane == 0 && wid < 5 && (nn != 0.0f || qq != 0.0f)) {
        atomicAdd(&sc_n, nn);
        atomicAdd(&sc_q, qq);
    }

    float s2 = 0.0f;
    if (tid < 128) {
        float t = ((sred[0][col] + sred[1][col]) + (sred[2][col] + sred[3][col]))
                + ((sred[4][col] + sred[5][col]) + (sred[6][col] + sred[7][col]));
        s2 = t * t;
    }
    #pragma unroll
    for (int o = 16; o; o >>= 1)
        s2 += __shfl_xor_sync(FULLMASK, s2, o);
    if (lane == 0 && wid < 4) sc_s2[wid] = s2;
    __syncthreads();

    if (tid == 0) {
        float S2 = (sc_s2[0] + sc_s2[1]) + (sc_s2[2] + sc_s2[3]);
        float Nn = sc_n;
        float Qq = sc_q;
        if (Nn > 1.0f) {
            float var = (Qq - S2 / Nn) / (Nn * 128.0f);
            atomicAdd(&g_tot, var);
            atomicAdd(&g_cntf, 1.0f);
        }
        __threadfence();
        unsigned my = atomicAdd(&g_done, 1u);
        if ((my & 127u) == 127u) {   // last of this launch's 128 blocks writes out
            float tt = atomicAdd(&g_tot,  0.0f);
            float cc = atomicAdd(&g_cntf, 0.0f);
            out[0] = (cc > 0.0f) ? (tt / cc) : 0.0f;
        }
    }
}

// ---------------------------------------------------------------------------
extern "C" void kernel_launch(void* const* d_in, const int* in_sizes, int n_in,
                              void* d_out, int out_size)
{
    (void)n_in; (void)out_size;
    const float* logits = (const float*)d_in[0];
    const int*   segs   = (const int*)d_in[1];
    const void*  mask   = d_in[2];
    const int N = in_sizes[1];   // B*T tokens

    k1_accumulate<<<GRID1, T1>>>(logits, segs, mask, N);
    k2_final<<<128, 1024>>>((float*)d_out);
}

// round 12
// speedup vs baseline: 1.1794x; 1.1794x over previous
#include <cuda_runtime.h>
#include <cstdint>

#define FULLMASK 0xFFFFFFFFu

constexpr int GRID1 = 148;           // one 512-thread block per SM (all co-resident)
constexpr int T1    = 512;           // 16 warps -> 128 regs/thread
constexpr int PART_STRIDE = 128 * 128 + 256;  // s[16384] + n[128] + Q[128]
constexpr int WIN   = 1024;          // token window (one window covers a block's chunk)
constexpr int LCAP  = WIN + 8;       // worklist capacity (worst case + pad slack)

// Partial accumulators: 148 * 16640 floats ~= 9.85 MB (static device array)
__device__ __align__(16) float g_part[(size_t)GRID1 * PART_STRIDE];
__device__ float g_tot;
__device__ float g_cntf;
__device__ unsigned g_arrive;        // monotonic grid-barrier counter (never reset)
__device__ unsigned g_done;          // monotonic finish counter (never reset)

// ---------------------------------------------------------------------------
// Fused kernel.
// Phase 1: smem worklists per warp (seg&15 == wid), batch-4 double-buffered
//          token processing, register-resident accumulators (8 rows/warp).
// Grid barrier (monotonic counter, LD.acquire polling).
// Phase 2: block c<128 reduces segment c across slabs -> variance -> total.
// ---------------------------------------------------------------------------
__global__ void __launch_bounds__(T1, 1)
k_fused(const float* __restrict__ logits,
        const int*   __restrict__ segs,
        const void*  __restrict__ maskp,
        int N, float* __restrict__ outp)
{
    __shared__ __align__(8) unsigned short lists[16][LCAP];
    __shared__ int   scnt[16];
    __shared__ float sred[4][128];
    __shared__ float sc_n, sc_q, sc_s2[4];

    const int tid  = threadIdx.x;
    const int lane = tid & 31;
    const int wid  = tid >> 5;   // 0..15

    if (blockIdx.x == 0 && tid == 0) { g_tot = 0.0f; g_cntf = 0.0f; }

    // --- Detect mask dtype (bool/uint8 vs int32) from byte pattern ---------
    int local_nz = 0;
    {
        const unsigned char* mb = (const unsigned char*)maskp;
        int lim = (N < 1024) ? N : 1024;
        for (int p = tid; p < lim; p += T1)
            if ((p & 3) && mb[p]) local_nz = 1;
    }
    const int is_bool = __syncthreads_or(local_nz);

    const int chunk = (N + GRID1 - 1) / GRID1;
    const int cbeg  = blockIdx.x * chunk;
    const int cend  = min(N, cbeg + chunk);

    const unsigned char* m8  = (const unsigned char*)maskp;
    const int*           m32 = (const int*)maskp;
    const float4* lg4 = (const float4*)logits;

    // --- Register accumulators: 8 owned segments per warp -------------------
    const float4 z4 = make_float4(0.f, 0.f, 0.f, 0.f);
    float4 a0 = z4, a1 = z4, a2 = z4, a3 = z4, a4 = z4, a5 = z4, a6 = z4, a7 = z4;
    float n0 = 0.f, n1 = 0.f, n2 = 0.f, n3 = 0.f, n4 = 0.f, n5 = 0.f, n6 = 0.f, n7 = 0.f;
    float q0 = 0.f, q1 = 0.f, q2 = 0.f, q3 = 0.f, q4 = 0.f, q5 = 0.f, q6 = 0.f, q7 = 0.f;

    for (int wb = cbeg; wb < cend; wb += WIN) {
        const int wlen = min(cend - wb, WIN);

        // ---------------- Build per-warp worklists --------------------------
        __syncthreads();                 // lists free (prev window done)
        if (tid < 16) scnt[tid] = 0;
        __syncthreads();
        for (int i = tid; i < wlen; i += T1) {
            int sg = segs[wb + i] & 127;
            int v  = is_bool ? (m8[wb + i] != 0) : (m32[wb + i] != 0);
            if (v) {
                int w   = sg & 15;
                int pos = atomicAdd(&scnt[w], 1);
                lists[w][pos] = (unsigned short)(i | ((sg >> 4) << 10));
            }
        }
        __syncthreads();

        // Pad this warp's list to a multiple of 4 with dead entries (bit 15).
        int cnt = scnt[wid];
        int pad = (4 - (cnt & 3)) & 3;
        if (lane < pad) lists[wid][cnt + lane] = (unsigned short)0x8000u;
        __syncwarp();
        const int tot = cnt + pad;

        // ---------------- Batch-4 double-buffered processing ----------------
        auto fetch = [&](int base, uint2& E,
                         float4& va, float4& vb, float4& vc, float4& vd) {
            E = *(const uint2*)&lists[wid][base];        // warp-uniform LDS.64
            int ta = (E.x      ) & 1023;
            int tb = (E.x >> 16) & 1023;
            int tc = (E.y      ) & 1023;
            int td = (E.y >> 16) & 1023;
            va = __ldg(lg4 + (size_t)(wb + ta) * 32 + lane);
            vb = __ldg(lg4 + (size_t)(wb + tb) * 32 + lane);
            vc = __ldg(lg4 + (size_t)(wb + tc) * 32 + lane);
            vd = __ldg(lg4 + (size_t)(wb + td) * 32 + lane);
        };

        auto process = [&](unsigned ent, float4 x) {
            const bool dead = (ent & 0x8000u) != 0;      // warp-uniform
            float4 e;
            e.x = __expf(x.x); e.y = __expf(x.y);
            e.z = __expf(x.z); e.w = __expf(x.w);
            float se = (e.x + e.y) + (e.z + e.w);
            float q  = (e.x*e.x + e.y*e.y) + (e.z*e.z + e.w*e.w);
            #pragma unroll
            for (int o = 16; o; o >>= 1) {
                se += __shfl_xor_sync(FULLMASK, se, o);
                q  += __shfl_xor_sync(FULLMASK, q,  o);
            }
            if (dead) return;
            const float inv = __frcp_rn(se);
            const float qn  = q * inv * inv;
            switch ((ent >> 10) & 7) {                   // warp-uniform row
            case 0: a0.x += e.x*inv; a0.y += e.y*inv; a0.z += e.z*inv; a0.w += e.w*inv;
                    n0 += 1.0f; q0 += qn; break;
            case 1: a1.x += e.x*inv; a1.y += e.y*inv; a1.z += e.z*inv; a1.w += e.w*inv;
                    n1 += 1.0f; q1 += qn; break;
            case 2: a2.x += e.x*inv; a2.y += e.y*inv; a2.z += e.z*inv; a2.w += e.w*inv;
                    n2 += 1.0f; q2 += qn; break;
            case 3: a3.x += e.x*inv; a3.y += e.y*inv; a3.z += e.z*inv; a3.w += e.w*inv;
                    n3 += 1.0f; q3 += qn; break;
            case 4: a4.x += e.x*inv; a4.y += e.y*inv; a4.z += e.z*inv; a4.w += e.w*inv;
                    n4 += 1.0f; q4 += qn; break;
            case 5: a5.x += e.x*inv; a5.y += e.y*inv; a5.z += e.z*inv; a5.w += e.w*inv;
                    n5 += 1.0f; q5 += qn; break;
            case 6: a6.x += e.x*inv; a6.y += e.y*inv; a6.z += e.z*inv; a6.w += e.w*inv;
                    n6 += 1.0f; q6 += qn; break;
            default:a7.x += e.x*inv; a7.y += e.y*inv; a7.z += e.z*inv; a7.w += e.w*inv;
                    n7 += 1.0f; q7 += qn; break;
            }
        };

        if (tot > 0) {
            uint2 Ec, En;
            float4 c0, c1, c2, c3, x0, x1, x2, x3;
            fetch(0, Ec, c0, c1, c2, c3);
            for (int b = 0; b < tot; b += 4) {
                if (b + 4 < tot) fetch(b + 4, En, x0, x1, x2, x3);
                process( Ec.x        & 0xFFFFu, c0);
                process((Ec.x >> 16) & 0xFFFFu, c1);
                process( Ec.y        & 0xFFFFu, c2);
                process((Ec.y >> 16) & 0xFFFFu, c3);
                Ec = En; c0 = x0; c1 = x1; c2 = x2; c3 = x3;
            }
        }
    }

    // --- Flush register accumulators straight to the global slab ------------
    {
        float* base = g_part + (size_t)blockIdx.x * PART_STRIDE;
        ((float4*)(base + (wid       ) * 128))[lane] = a0;
        ((float4*)(base + (wid +  16 ) * 128))[lane] = a1;
        ((float4*)(base + (wid +  32 ) * 128))[lane] = a2;
        ((float4*)(base + (wid +  48 ) * 128))[lane] = a3;
        ((float4*)(base + (wid +  64 ) * 128))[lane] = a4;
        ((float4*)(base + (wid +  80 ) * 128))[lane] = a5;
        ((float4*)(base + (wid +  96 ) * 128))[lane] = a6;
        ((float4*)(base + (wid + 112 ) * 128))[lane] = a7;
        if (lane == 0) {
            base[16384 + wid      ] = n0;  base[16512 + wid      ] = q0;
            base[16384 + wid +  16] = n1;  base[16512 + wid +  16] = q1;
            base[16384 + wid +  32] = n2;  base[16512 + wid +  32] = q2;
            base[16384 + wid +  48] = n3;  base[16512 + wid +  48] = q3;
            base[16384 + wid +  64] = n4;  base[16512 + wid +  64] = q4;
            base[16384 + wid +  80] = n5;  base[16512 + wid +  80] = q5;
            base[16384 + wid +  96] = n6;  base[16512 + wid +  96] = q6;
            base[16384 + wid + 112] = n7;  base[16512 + wid + 112] = q7;
        }
    }

    // ======================= GRID BARRIER ===================================
    // Monotonic counter (graph-replay safe); LD.acquire polling + backoff.
    // All 148 blocks co-resident (grid == #SMs, occ 1) => no deadlock.
    __syncthreads();
    if (tid == 0) {
        __threadfence();
        unsigned my = atomicAdd(&g_arrive, 1u);
        unsigned target = (my / GRID1 + 1u) * GRID1;
        for (;;) {
            unsigned v;
            asm volatile("ld.acquire.gpu.global.u32 %0, [%1];"
                         : "=r"(v) : "l"(&g_arrive));
            if (v >= target) break;
            __nanosleep(64);
        }
    }
    __syncthreads();

    // ======================= PHASE 2: segment reduction =====================
    const int c = blockIdx.x;
    if (c < 128) {
        if (tid == 0) { sc_n = 0.0f; sc_q = 0.0f; }

        const int col = tid & 127;       // column within the segment row
        const int grp = tid >> 7;        // 0..3 slab groups (37 slabs each)

        float sj = 0.0f;
        #pragma unroll
        for (int b = grp; b < GRID1; b += 4)
            sj += g_part[(size_t)b * PART_STRIDE + c * 128 + col];
        sred[grp][col] = sj;

        float nn = 0.0f, qq = 0.0f;
        if (tid < GRID1) {
            nn = g_part[(size_t)tid * PART_STRIDE + 16384 + c];
            qq = g_part[(size_t)tid * PART_STRIDE + 16512 + c];
        }
        #pragma unroll
        for (int o = 16; o; o >>= 1) {
            nn += __shfl_xor_sync(FULLMASK, nn, o);
            qq += __shfl_xor_sync(FULLMASK, qq, o);
        }
        __syncthreads();
        if (lane == 0 && wid < 5 && (nn != 0.0f || qq != 0.0f)) {
            atomicAdd(&sc_n, nn);
            atomicAdd(&sc_q, qq);
        }

        float s2 = 0.0f;
        if (tid < 128) {
            float t = (sred[0][col] + sred[1][col]) + (sred[2][col] + sred[3][col]);
            s2 = t * t;
        }
        #pragma unroll
        for (int o = 16; o; o >>= 1)
            s2 += __shfl_xor_sync(FULLMASK, s2, o);
        if (lane == 0 && wid < 4) sc_s2[wid] = s2;
        __syncthreads();

        if (tid == 0) {
            float S2 = (sc_s2[0] + sc_s2[1]) + (sc_s2[2] + sc_s2[3]);
            float Nn = sc_n;
            float Qq = sc_q;
            if (Nn > 1.0f) {
                float var = (Qq - S2 / Nn) / (Nn * 128.0f);
                atomicAdd(&g_tot, var);
                atomicAdd(&g_cntf, 1.0f);
            }
            __threadfence();
            unsigned my = atomicAdd(&g_done, 1u);
            if ((my & 127u) == 127u) {   // last of this launch's 128 writes out
                float tt = atomicAdd(&g_tot,  0.0f);
                float cc = atomicAdd(&g_cntf, 0.0f);
                outp[0] = (cc > 0.0f) ? (tt / cc) : 0.0f;
            }
        }
    }
}

// ---------------------------------------------------------------------------
extern "C" void kernel_launch(void* const* d_in, const int* in_sizes, int n_in,
                              void* d_out, int out_size)
{
    (void)n_in; (void)out_size;
    const float* logits = (const float*)d_in[0];
    const int*   segs   = (const int*)d_in[1];
    const void*  mask   = d_in[2];
    const int N = in_sizes[1];   // B*T tokens

    k_fused<<<GRID1, T1>>>(logits, segs, mask, N, (float*)d_out);
}